// round 3
// baseline (speedup 1.0000x reference)
#include <cuda_runtime.h>
#include <cuda_bf16.h>
#include <math.h>

// Problem constants
#define Bb 4
#define Tt 2048
#define Cc 1024
#define Hh 16
#define Dd 64
#define FFN 4096
#define ROWS (Bb*Tt)          // 8192

// ---------------- scratch (device globals; no allocation allowed) ----------
__device__ float g_xn  [ROWS*Cc];
__device__ float g_q   [ROWS*Cc];
__device__ float g_k   [ROWS*Cc];
__device__ float g_v   [ROWS*Cc];
__device__ float g_gate[ROWS*Cc];
__device__ float g_o   [ROWS*Cc];
__device__ float g_beta[ROWS*Hh];
__device__ float g_g   [ROWS*FFN];
__device__ float g_u   [ROWS*FFN];

// ---------------- helpers ----------------
__device__ __forceinline__ float sigmoidf_(float v) { return 1.f / (1.f + __expf(-v)); }

// ---------------- RMSNorm: one block per row of 1024 ----------------
__global__ void __launch_bounds__(256) rmsnorm_kernel(const float* __restrict__ x,
                                                      const float* __restrict__ w,
                                                      float* __restrict__ y) {
    int row = blockIdx.x;
    const float4* xr = (const float4*)(x + (size_t)row * Cc);
    const float4* wr = (const float4*)w;
    int tid = threadIdx.x;
    float4 v = xr[tid];
    float s = v.x*v.x + v.y*v.y + v.z*v.z + v.w*v.w;
    #pragma unroll
    for (int off = 16; off; off >>= 1) s += __shfl_xor_sync(0xffffffffu, s, off);
    __shared__ float red[8];
    int wid = tid >> 5, lane = tid & 31;
    if (lane == 0) red[wid] = s;
    __syncthreads();
    float tot = 0.f;
    #pragma unroll
    for (int i = 0; i < 8; i++) tot += red[i];
    float inv = rsqrtf(tot * (1.f / Cc) + 1e-6f);
    float4 wv = wr[tid];
    float4 o;
    o.x = v.x * inv * wv.x; o.y = v.y * inv * wv.y;
    o.z = v.z * inv * wv.z; o.w = v.w * inv * wv.w;
    ((float4*)(y + (size_t)row * Cc))[tid] = o;
}

// ---------------- L2 norm over last dim (64) of (B,T,H,D); one warp/vector --
__global__ void __launch_bounds__(256) l2norm_kernel(float* __restrict__ q) {
    int vec = blockIdx.x * 8 + (threadIdx.x >> 5);
    int lane = threadIdx.x & 31;
    float2* p = (float2*)(q + (size_t)vec * Dd) + lane;
    float2 v = *p;
    float s = v.x*v.x + v.y*v.y;
    #pragma unroll
    for (int off = 16; off; off >>= 1) s += __shfl_xor_sync(0xffffffffu, s, off);
    float inv = 1.f / fmaxf(sqrtf(s), 1e-12f);
    v.x *= inv; v.y *= inv;
    *p = v;
}

// ---------------- beta = sigmoid(xn @ beta_w.T + beta_b); one block/row ----
__global__ void __launch_bounds__(512) beta_kernel(const float* __restrict__ xn,
                                                   const float* __restrict__ bw,
                                                   const float* __restrict__ bb,
                                                   float* __restrict__ beta) {
    int row = blockIdx.x;
    __shared__ float xs[Cc];
    int tid = threadIdx.x;
    ((float2*)xs)[tid] = ((const float2*)(xn + (size_t)row * Cc))[tid];
    __syncthreads();
    int w = tid >> 5, lane = tid & 31;
    const float* wr = bw + (size_t)w * Cc;
    float s = 0.f;
    #pragma unroll 8
    for (int c = lane; c < Cc; c += 32) s += xs[c] * wr[c];
    #pragma unroll
    for (int off = 16; off; off >>= 1) s += __shfl_xor_sync(0xffffffffu, s, off);
    if (lane == 0) beta[(size_t)row * Hh + w] = sigmoidf_(s + bb[w]);
}

// ---------------- GatedDeltaNet scan: one block per (b,h), 64 threads ------
__global__ void __launch_bounds__(64) scan_kernel(const float* __restrict__ q,
                                                  const float* __restrict__ k,
                                                  const float* __restrict__ v,
                                                  const float* __restrict__ beta,
                                                  float* __restrict__ o) {
    int b = blockIdx.x >> 4;
    int h = blockIdx.x & 15;
    int d = threadIdx.x;
    const size_t base = ((size_t)b * Tt) * Cc + h * Dd;
    __shared__ float qs[Dd], ks[Dd];
    float Mr[Dd];
    #pragma unroll
    for (int c = 0; c < Dd; c++) Mr[c] = 0.f;
    for (int t = 0; t < Tt; t++) {
        size_t idx = base + (size_t)t * Cc + d;
        qs[d] = q[idx];
        ks[d] = k[idx];
        float vv = v[idx];
        float bt = beta[((size_t)b * Tt + t) * Hh + h];
        __syncthreads();
        float o0 = 0.f, o1 = 0.f, o2 = 0.f, o3 = 0.f;
        float a0 = 0.f, a1 = 0.f, a2 = 0.f, a3 = 0.f;
        #pragma unroll
        for (int c = 0; c < Dd; c += 4) {
            o0 += Mr[c+0] * qs[c+0]; a0 += Mr[c+0] * ks[c+0];
            o1 += Mr[c+1] * qs[c+1]; a1 += Mr[c+1] * ks[c+1];
            o2 += Mr[c+2] * qs[c+2]; a2 += Mr[c+2] * ks[c+2];
            o3 += Mr[c+3] * qs[c+3]; a3 += Mr[c+3] * ks[c+3];
        }
        float oacc = (o0 + o1) + (o2 + o3);
        float kacc = (a0 + a1) + (a2 + a3);
        float coef = bt * (vv - kacc);
        #pragma unroll
        for (int c = 0; c < Dd; c++) Mr[c] += coef * ks[c];
        o[idx] = oacc;
        __syncthreads();
    }
}

// ---------------- Tiled fp32 GEMM (NT): C[M,N] = epi(A*B^T) (+res) ---------
// A: M x K row-major (optionally elementwise-multiplied by A2)
// B: N x K row-major
// EPI: 0 none, 1 sigmoid, 2 silu     (applied before residual add)
#define BM 128
#define BN 128
#define BK 16
#define TM 8
#define TN 8

template<int EPI, bool HAS_A2, bool HAS_RES>
__global__ void __launch_bounds__(256) gemm_nt(const float* __restrict__ A,
                                               const float* __restrict__ A2,
                                               const float* __restrict__ B,
                                               const float* __restrict__ res,
                                               float* __restrict__ C,
                                               int M, int N, int K) {
    __shared__ float As[BK][BM];
    __shared__ float Bs[BK][BN];
    int tid = threadIdx.x;
    int brow = blockIdx.y * BM;
    int bcol = blockIdx.x * BN;
    int tr = (tid >> 4) * TM;
    int tc = (tid & 15) * TN;

    const float* Aptr  = A + (size_t)brow * K;
    const float* A2ptr = HAS_A2 ? (A2 + (size_t)brow * K) : nullptr;
    const float* Bptr  = B + (size_t)bcol * K;

    float acc[TM][TN];
    #pragma unroll
    for (int i = 0; i < TM; i++)
        #pragma unroll
        for (int j = 0; j < TN; j++) acc[i][j] = 0.f;

    for (int kb = 0; kb < K; kb += BK) {
        #pragma unroll
        for (int i = 0; i < 2; i++) {
            int f   = tid * 2 + i;          // 0..511 float4 slots
            int row = f >> 2;               // 0..127
            int k4  = (f & 3) * 4;          // 0,4,8,12
            float4 va = *(const float4*)(Aptr + (size_t)row * K + kb + k4);
            if (HAS_A2) {
                float4 v2 = *(const float4*)(A2ptr + (size_t)row * K + kb + k4);
                va.x *= v2.x; va.y *= v2.y; va.z *= v2.z; va.w *= v2.w;
            }
            As[k4+0][row] = va.x; As[k4+1][row] = va.y;
            As[k4+2][row] = va.z; As[k4+3][row] = va.w;
            float4 vb = *(const float4*)(Bptr + (size_t)row * K + kb + k4);
            Bs[k4+0][row] = vb.x; Bs[k4+1][row] = vb.y;
            Bs[k4+2][row] = vb.z; Bs[k4+3][row] = vb.w;
        }
        __syncthreads();
        #pragma unroll
        for (int kk = 0; kk < BK; kk++) {
            float ar[TM], br[TN];
            #pragma unroll
            for (int i = 0; i < TM; i++) ar[i] = As[kk][tr + i];
            #pragma unroll
            for (int j = 0; j < TN; j++) br[j] = Bs[kk][tc + j];
            #pragma unroll
            for (int i = 0; i < TM; i++)
                #pragma unroll
                for (int j = 0; j < TN; j++)
                    acc[i][j] = fmaf(ar[i], br[j], acc[i][j]);
        }
        __syncthreads();
    }

    #pragma unroll
    for (int i = 0; i < TM; i++) {
        size_t r = (size_t)(brow + tr + i);
        #pragma unroll
        for (int j = 0; j < TN; j++) {
            size_t cidx = r * N + bcol + tc + j;
            float v = acc[i][j];
            if (EPI == 1) v = sigmoidf_(v);
            else if (EPI == 2) v = v * sigmoidf_(v);
            if (HAS_RES) v += res[cidx];
            C[cidx] = v;
        }
    }
}

// ---------------- launcher ----------------
extern "C" void kernel_launch(void* const* d_in, const int* in_sizes, int n_in,
                              void* d_out, int out_size) {
    const float* x        = (const float*)d_in[0];
    // d_in[1]=cos, d_in[2]=sin  (unused for layer_idx=0)
    const float* norm1_w  = (const float*)d_in[3];
    const float* norm2_w  = (const float*)d_in[4];
    const float* q_w      = (const float*)d_in[5];
    const float* k_w      = (const float*)d_in[6];
    const float* v_w      = (const float*)d_in[7];
    const float* beta_w   = (const float*)d_in[8];
    const float* beta_b   = (const float*)d_in[9];
    const float* gate_w   = (const float*)d_in[10];
    const float* o_w      = (const float*)d_in[11];
    const float* ffn_gate = (const float*)d_in[12];
    const float* ffn_up   = (const float*)d_in[13];
    const float* ffn_down = (const float*)d_in[14];
    float* out = (float*)d_out;

    float *xn, *q, *k, *v, *gate, *o, *beta, *g, *u;
    cudaGetSymbolAddress((void**)&xn,   g_xn);
    cudaGetSymbolAddress((void**)&q,    g_q);
    cudaGetSymbolAddress((void**)&k,    g_k);
    cudaGetSymbolAddress((void**)&v,    g_v);
    cudaGetSymbolAddress((void**)&gate, g_gate);
    cudaGetSymbolAddress((void**)&o,    g_o);
    cudaGetSymbolAddress((void**)&beta, g_beta);
    cudaGetSymbolAddress((void**)&g,    g_g);
    cudaGetSymbolAddress((void**)&u,    g_u);

    dim3 blk(256);
    dim3 grid_c(Cc / BN, ROWS / BM);    // N=1024
    dim3 grid_f(FFN / BN, ROWS / BM);   // N=4096

    // 1. xn1 = rmsnorm(x, norm1_w)
    rmsnorm_kernel<<<ROWS, 256>>>(x, norm1_w, xn);

    // 2. projections
    gemm_nt<0, false, false><<<grid_c, blk>>>(xn, nullptr, q_w,    nullptr, q,    ROWS, Cc, Cc);
    gemm_nt<0, false, false><<<grid_c, blk>>>(xn, nullptr, k_w,    nullptr, k,    ROWS, Cc, Cc);
    gemm_nt<0, false, false><<<grid_c, blk>>>(xn, nullptr, v_w,    nullptr, v,    ROWS, Cc, Cc);
    gemm_nt<1, false, false><<<grid_c, blk>>>(xn, nullptr, gate_w, nullptr, gate, ROWS, Cc, Cc);
    beta_kernel<<<ROWS, 512>>>(xn, beta_w, beta_b, beta);

    // 3. l2 normalize q, k per head
    l2norm_kernel<<<(ROWS * Hh) / 8, 256>>>(q);
    l2norm_kernel<<<(ROWS * Hh) / 8, 256>>>(k);

    // 4. sequential delta-rule scan
    scan_kernel<<<Bb * Hh, Dd>>>(q, k, v, beta, o);

    // 5. x1 = x + (gate*o) @ o_w.T     -> out
    gemm_nt<0, true, true><<<grid_c, blk>>>(gate, o, o_w, x, out, ROWS, Cc, Cc);

    // 6. xn2 = rmsnorm(x1, norm2_w)
    rmsnorm_kernel<<<ROWS, 256>>>(out, norm2_w, xn);

    // 7. FFN: g = silu(xn2 @ Wg.T); u = xn2 @ Wu.T; out += (g*u) @ Wd.T
    gemm_nt<2, false, false><<<grid_f, blk>>>(xn, nullptr, ffn_gate, nullptr, g, ROWS, FFN, Cc);
    gemm_nt<0, false, false><<<grid_f, blk>>>(xn, nullptr, ffn_up,   nullptr, u, ROWS, FFN, Cc);
    gemm_nt<0, true, true><<<grid_c, blk>>>(g, u, ffn_down, out, out, ROWS, Cc, FFN);
}

// round 6
// speedup vs baseline: 1.6428x; 1.6428x over previous
#include <cuda_runtime.h>
#include <cuda_bf16.h>
#include <math.h>
#include <stdint.h>

// Problem constants
#define Bb 4
#define Tt 2048
#define Cc 1024
#define Hh 16
#define Dd 64
#define FFN 4096
#define ROWS (Bb*Tt)          // 8192

// ---------------- scratch (device globals; no allocation allowed) ----------
__device__ float g_xn  [ROWS*Cc];
__device__ float g_q   [ROWS*Cc];
__device__ float g_k   [ROWS*Cc];
__device__ float g_v   [ROWS*Cc];
__device__ float g_gate[ROWS*Cc];
__device__ float g_o   [ROWS*Cc];
__device__ float g_beta[ROWS*Hh];
__device__ float g_g   [ROWS*FFN];
__device__ float g_u   [ROWS*FFN];

// ---------------- helpers ----------------
__device__ __forceinline__ float sigmoidf_(float v) { return 1.f / (1.f + __expf(-v)); }

__device__ __forceinline__ uint32_t smem_u32(const void* p) {
    uint32_t a;
    asm("{ .reg .u64 t; cvta.to.shared.u64 t, %1; cvt.u32.u64 %0, t; }" : "=r"(a) : "l"(p));
    return a;
}
__device__ __forceinline__ void cp_async16(uint32_t dst, const void* src) {
    asm volatile("cp.async.cg.shared.global [%0], [%1], 16;" :: "r"(dst), "l"(src) : "memory");
}
__device__ __forceinline__ void cp_commit() {
    asm volatile("cp.async.commit_group;" ::: "memory");
}
__device__ __forceinline__ uint32_t to_tf32(float f) {
    uint32_t r;
    asm("cvt.rna.tf32.f32 %0, %1;" : "=r"(r) : "f"(f));
    return r;
}
__device__ __forceinline__ void mma_tf32(float* d, const uint32_t* a, const uint32_t* b) {
    asm volatile(
        "mma.sync.aligned.m16n8k8.row.col.f32.tf32.tf32.f32 "
        "{%0,%1,%2,%3}, {%4,%5,%6,%7}, {%8,%9}, {%0,%1,%2,%3};"
        : "+f"(d[0]), "+f"(d[1]), "+f"(d[2]), "+f"(d[3])
        : "r"(a[0]), "r"(a[1]), "r"(a[2]), "r"(a[3]), "r"(b[0]), "r"(b[1]));
}

// ---------------- RMSNorm: one block per row of 1024 ----------------
__global__ void __launch_bounds__(256) rmsnorm_kernel(const float* __restrict__ x,
                                                      const float* __restrict__ w,
                                                      float* __restrict__ y) {
    int row = blockIdx.x;
    const float4* xr = (const float4*)(x + (size_t)row * Cc);
    const float4* wr = (const float4*)w;
    int tid = threadIdx.x;
    float4 v = xr[tid];
    float s = v.x*v.x + v.y*v.y + v.z*v.z + v.w*v.w;
    #pragma unroll
    for (int off = 16; off; off >>= 1) s += __shfl_xor_sync(0xffffffffu, s, off);
    __shared__ float red[8];
    int wid = tid >> 5, lane = tid & 31;
    if (lane == 0) red[wid] = s;
    __syncthreads();
    float tot = 0.f;
    #pragma unroll
    for (int i = 0; i < 8; i++) tot += red[i];
    float inv = rsqrtf(tot * (1.f / Cc) + 1e-6f);
    float4 wv = wr[tid];
    float4 o;
    o.x = v.x * inv * wv.x; o.y = v.y * inv * wv.y;
    o.z = v.z * inv * wv.z; o.w = v.w * inv * wv.w;
    ((float4*)(y + (size_t)row * Cc))[tid] = o;
}

// ---------------- L2 norm over last dim (64); one warp/vector --------------
__global__ void __launch_bounds__(256) l2norm_kernel(float* __restrict__ q) {
    int vec = blockIdx.x * 8 + (threadIdx.x >> 5);
    int lane = threadIdx.x & 31;
    float2* p = (float2*)(q + (size_t)vec * Dd) + lane;
    float2 v = *p;
    float s = v.x*v.x + v.y*v.y;
    #pragma unroll
    for (int off = 16; off; off >>= 1) s += __shfl_xor_sync(0xffffffffu, s, off);
    float inv = 1.f / fmaxf(sqrtf(s), 1e-12f);
    v.x *= inv; v.y *= inv;
    *p = v;
}

// ---------------- beta = sigmoid(xn @ beta_w.T + beta_b) ----
__global__ void __launch_bounds__(512) beta_kernel(const float* __restrict__ xn,
                                                   const float* __restrict__ bw,
                                                   const float* __restrict__ bb,
                                                   float* __restrict__ beta) {
    int row = blockIdx.x;
    __shared__ float xs[Cc];
    int tid = threadIdx.x;
    ((float2*)xs)[tid] = ((const float2*)(xn + (size_t)row * Cc))[tid];
    __syncthreads();
    int w = tid >> 5, lane = tid & 31;
    const float* wr = bw + (size_t)w * Cc;
    float s = 0.f;
    #pragma unroll 8
    for (int c = lane; c < Cc; c += 32) s += xs[c] * wr[c];
    #pragma unroll
    for (int off = 16; off; off >>= 1) s += __shfl_xor_sync(0xffffffffu, s, off);
    if (lane == 0) beta[(size_t)row * Hh + w] = sigmoidf_(s + bb[w]);
}

// ---------------- GatedDeltaNet scan: one block per (b,h), 64 threads ------
__global__ void __launch_bounds__(64) scan_kernel(const float* __restrict__ q,
                                                  const float* __restrict__ k,
                                                  const float* __restrict__ v,
                                                  const float* __restrict__ beta,
                                                  float* __restrict__ o) {
    int b = blockIdx.x >> 4;
    int h = blockIdx.x & 15;
    int d = threadIdx.x;
    const size_t base = ((size_t)b * Tt) * Cc + h * Dd;
    __shared__ float qs[Dd], ks[Dd];
    float Mr[Dd];
    #pragma unroll
    for (int c = 0; c < Dd; c++) Mr[c] = 0.f;
    for (int t = 0; t < Tt; t++) {
        size_t idx = base + (size_t)t * Cc + d;
        qs[d] = q[idx];
        ks[d] = k[idx];
        float vv = v[idx];
        float bt = beta[((size_t)b * Tt + t) * Hh + h];
        __syncthreads();
        float o0 = 0.f, o1 = 0.f, o2 = 0.f, o3 = 0.f;
        float a0 = 0.f, a1 = 0.f, a2 = 0.f, a3 = 0.f;
        #pragma unroll
        for (int c = 0; c < Dd; c += 4) {
            o0 += Mr[c+0] * qs[c+0]; a0 += Mr[c+0] * ks[c+0];
            o1 += Mr[c+1] * qs[c+1]; a1 += Mr[c+1] * ks[c+1];
            o2 += Mr[c+2] * qs[c+2]; a2 += Mr[c+2] * ks[c+2];
            o3 += Mr[c+3] * qs[c+3]; a3 += Mr[c+3] * ks[c+3];
        }
        float oacc = (o0 + o1) + (o2 + o3);
        float kacc = (a0 + a1) + (a2 + a3);
        float coef = bt * (vv - kacc);
        #pragma unroll
        for (int c = 0; c < Dd; c++) Mr[c] += coef * ks[c];
        o[idx] = oacc;
        __syncthreads();
    }
}

// ============ tf32 mma.sync GEMM (NT): C = epi(A*B^T) (+res) ===============
// A: M x K row-major (optionally multiplied elementwise by A2)
// B: N x K row-major
// Tile 128x128x32. 256 threads = 8 warps (4 m x 2 n), warp tile 32x64.
// SMEM row stride 36 floats: conflict-free fragment LDS + 16B-aligned rows.
// epi: 0 none, 1 sigmoid, 2 silu
#define GBM 128
#define GBN 128
#define GBK 32
#define LDS_STRIDE 36                                  // floats
#define TILE_FLOATS (128 * LDS_STRIDE)                 // 4608
#define TILE_BYTES  (TILE_FLOATS * 4)                  // 18432
#define STAGE_FLOATS (2 * TILE_FLOATS)
#define STAGE_BYTES  (2 * TILE_BYTES)                  // 36864
#define GEMM_SMEM    (2 * STAGE_BYTES)                 // 73728

template<bool HAS_A2, bool HAS_RES>
__device__ __forceinline__ void gemm_core(const float* __restrict__ A,
                                          const float* __restrict__ A2,
                                          const float* __restrict__ B,
                                          const float* __restrict__ res,
                                          float* __restrict__ C,
                                          int N, int K, int epi) {
    extern __shared__ float smem[];
    const uint32_t s0 = smem_u32(smem);

    const int tid  = threadIdx.x;
    const int wid  = tid >> 5;
    const int lane = tid & 31;
    const int warp_m = wid >> 1;          // 0..3  (rows of 32)
    const int warp_n = wid & 1;           // 0..1  (cols of 64)
    const int gid  = lane >> 2;           // 0..7
    const int qid  = lane & 3;            // 0..3

    const int brow = blockIdx.y * GBM;
    const int bcol = blockIdx.x * GBN;

    const float* Aptr  = A + (size_t)brow * K;
    const float* A2ptr = HAS_A2 ? (A2 + (size_t)brow * K) : nullptr;
    const float* Bptr  = B + (size_t)bcol * K;

    float acc[2][8][4];
    #pragma unroll
    for (int m = 0; m < 2; m++)
        #pragma unroll
        for (int n = 0; n < 8; n++)
            #pragma unroll
            for (int c = 0; c < 4; c++) acc[m][n][c] = 0.f;

    const int nk = K >> 5;

    // ---- fill stage st with K-tile kb ----
    auto fill = [&](int kb, int st) {
        const uint32_t aB = s0 + st * STAGE_BYTES;
        const uint32_t bB = aB + TILE_BYTES;
        const int koff = kb * GBK;
        if (!HAS_A2) {
            #pragma unroll
            for (int i = 0; i < 4; i++) {
                int c = tid + i * 256;              // 0..1023 16B chunks
                int row = c >> 3, cp = c & 7;
                cp_async16(aB + row * (LDS_STRIDE*4) + cp * 16,
                           Aptr + (size_t)row * K + koff + cp * 4);
            }
        } else {
            #pragma unroll
            for (int i = 0; i < 4; i++) {
                int c = tid + i * 256;
                int row = c >> 3, cp = c & 7;
                float4 va = *(const float4*)(Aptr  + (size_t)row * K + koff + cp * 4);
                float4 v2 = *(const float4*)(A2ptr + (size_t)row * K + koff + cp * 4);
                va.x *= v2.x; va.y *= v2.y; va.z *= v2.z; va.w *= v2.w;
                *(float4*)((char*)smem + (st * STAGE_BYTES) + row * (LDS_STRIDE*4) + cp * 16) = va;
            }
        }
        #pragma unroll
        for (int i = 0; i < 4; i++) {
            int c = tid + i * 256;
            int row = c >> 3, cp = c & 7;
            cp_async16(bB + row * (LDS_STRIDE*4) + cp * 16,
                       Bptr + (size_t)row * K + koff + cp * 4);
        }
        cp_commit();
    };

    fill(0, 0);

    for (int kb = 0; kb < nk; kb++) {
        const int cur = kb & 1;
        if (kb + 1 < nk) {
            fill(kb + 1, cur ^ 1);
            asm volatile("cp.async.wait_group 1;" ::: "memory");
        } else {
            asm volatile("cp.async.wait_group 0;" ::: "memory");
        }
        __syncthreads();

        const float* sA = smem + cur * STAGE_FLOATS;
        const float* sB = sA + TILE_FLOATS;

        #pragma unroll
        for (int ks = 0; ks < 4; ks++) {
            const int k0 = ks * 8 + qid;
            uint32_t afr[2][4];
            #pragma unroll
            for (int m = 0; m < 2; m++) {
                int r = warp_m * 32 + m * 16 + gid;
                afr[m][0] = to_tf32(sA[(r)     * LDS_STRIDE + k0]);
                afr[m][1] = to_tf32(sA[(r + 8) * LDS_STRIDE + k0]);
                afr[m][2] = to_tf32(sA[(r)     * LDS_STRIDE + k0 + 4]);
                afr[m][3] = to_tf32(sA[(r + 8) * LDS_STRIDE + k0 + 4]);
            }
            #pragma unroll
            for (int n = 0; n < 8; n++) {
                int cn = warp_n * 64 + n * 8 + gid;
                uint32_t bfr[2];
                bfr[0] = to_tf32(sB[cn * LDS_STRIDE + k0]);
                bfr[1] = to_tf32(sB[cn * LDS_STRIDE + k0 + 4]);
                mma_tf32(acc[0][n], afr[0], bfr);
                mma_tf32(acc[1][n], afr[1], bfr);
            }
        }
        __syncthreads();
    }

    // ---- epilogue ----
    #pragma unroll
    for (int m = 0; m < 2; m++) {
        const size_t r0 = (size_t)(brow + warp_m * 32 + m * 16 + gid);
        const size_t r1 = r0 + 8;
        #pragma unroll
        for (int n = 0; n < 8; n++) {
            const int col = bcol + warp_n * 64 + n * 8 + qid * 2;
            float v0 = acc[m][n][0], v1 = acc[m][n][1];
            float v2 = acc[m][n][2], v3 = acc[m][n][3];
            if (epi == 1) {
                v0 = sigmoidf_(v0); v1 = sigmoidf_(v1);
                v2 = sigmoidf_(v2); v3 = sigmoidf_(v3);
            } else if (epi == 2) {
                v0 *= sigmoidf_(v0); v1 *= sigmoidf_(v1);
                v2 *= sigmoidf_(v2); v3 *= sigmoidf_(v3);
            }
            if (HAS_RES) {
                float2 ra = *(const float2*)(res + r0 * N + col);
                float2 rb = *(const float2*)(res + r1 * N + col);
                v0 += ra.x; v1 += ra.y; v2 += rb.x; v3 += rb.y;
            }
            *(float2*)(C + r0 * N + col) = make_float2(v0, v1);
            *(float2*)(C + r1 * N + col) = make_float2(v2, v3);
        }
    }
}

template<int EPI, bool HAS_A2, bool HAS_RES>
__global__ void __launch_bounds__(256) gemm_one(const float* __restrict__ A,
                                                const float* __restrict__ A2,
                                                const float* __restrict__ B,
                                                const float* __restrict__ res,
                                                float* __restrict__ C,
                                                int N, int K) {
    gemm_core<HAS_A2, HAS_RES>(A, A2, B, res, C, N, K, EPI);
}

// fused q/k/v/gate projections: blockIdx.z selects weight/output; z==3 -> sigmoid
__global__ void __launch_bounds__(256) gemm_qkvg(const float* __restrict__ A,
                                                 const float* __restrict__ B0,
                                                 const float* __restrict__ B1,
                                                 const float* __restrict__ B2,
                                                 const float* __restrict__ B3,
                                                 float* __restrict__ C0,
                                                 float* __restrict__ C1,
                                                 float* __restrict__ C2,
                                                 float* __restrict__ C3) {
    int z = blockIdx.z;
    const float* B = (z == 0) ? B0 : (z == 1) ? B1 : (z == 2) ? B2 : B3;
    float*       C = (z == 0) ? C0 : (z == 1) ? C1 : (z == 2) ? C2 : C3;
    gemm_core<false, false>(A, nullptr, B, nullptr, C, Cc, Cc, (z == 3) ? 1 : 0);
}

// fused ffn gate/up: z==0 -> silu into g, z==1 -> plain into u
__global__ void __launch_bounds__(256) gemm_gu(const float* __restrict__ A,
                                               const float* __restrict__ Bg,
                                               const float* __restrict__ Bu,
                                               float* __restrict__ Cg,
                                               float* __restrict__ Cu) {
    int z = blockIdx.z;
    gemm_core<false, false>(A, nullptr, z ? Bu : Bg, nullptr, z ? Cu : Cg,
                            FFN, Cc, z ? 0 : 2);
}

// ---------------- launcher ----------------
extern "C" void kernel_launch(void* const* d_in, const int* in_sizes, int n_in,
                              void* d_out, int out_size) {
    const float* x        = (const float*)d_in[0];
    // d_in[1]=cos, d_in[2]=sin  (unused for layer_idx=0)
    const float* norm1_w  = (const float*)d_in[3];
    const float* norm2_w  = (const float*)d_in[4];
    const float* q_w      = (const float*)d_in[5];
    const float* k_w      = (const float*)d_in[6];
    const float* v_w      = (const float*)d_in[7];
    const float* beta_w   = (const float*)d_in[8];
    const float* beta_b   = (const float*)d_in[9];
    const float* gate_w   = (const float*)d_in[10];
    const float* o_w      = (const float*)d_in[11];
    const float* ffn_gate = (const float*)d_in[12];
    const float* ffn_up   = (const float*)d_in[13];
    const float* ffn_down = (const float*)d_in[14];
    float* out = (float*)d_out;

    float *xn, *q, *k, *v, *gate, *o, *beta, *g, *u;
    cudaGetSymbolAddress((void**)&xn,   g_xn);
    cudaGetSymbolAddress((void**)&q,    g_q);
    cudaGetSymbolAddress((void**)&k,    g_k);
    cudaGetSymbolAddress((void**)&v,    g_v);
    cudaGetSymbolAddress((void**)&gate, g_gate);
    cudaGetSymbolAddress((void**)&o,    g_o);
    cudaGetSymbolAddress((void**)&beta, g_beta);
    cudaGetSymbolAddress((void**)&g,    g_g);
    cudaGetSymbolAddress((void**)&u,    g_u);

    cudaFuncSetAttribute(gemm_qkvg,              cudaFuncAttributeMaxDynamicSharedMemorySize, GEMM_SMEM);
    cudaFuncSetAttribute(gemm_gu,                cudaFuncAttributeMaxDynamicSharedMemorySize, GEMM_SMEM);
    cudaFuncSetAttribute(gemm_one<0,true,true>,  cudaFuncAttributeMaxDynamicSharedMemorySize, GEMM_SMEM);

    dim3 blk(256);
    dim3 grid_qkvg(Cc / GBN, ROWS / GBM, 4);   // 8 x 64 x 4
    dim3 grid_c(Cc / GBN, ROWS / GBM);         // 8 x 64
    dim3 grid_gu(FFN / GBN, ROWS / GBM, 2);    // 32 x 64 x 2

    // 1. xn1 = rmsnorm(x, norm1_w)
    rmsnorm_kernel<<<ROWS, 256>>>(x, norm1_w, xn);

    // 2. fused q/k/v/gate projections (+ sigmoid on gate)
    gemm_qkvg<<<grid_qkvg, blk, GEMM_SMEM>>>(xn, q_w, k_w, v_w, gate_w, q, k, v, gate);
    beta_kernel<<<ROWS, 512>>>(xn, beta_w, beta_b, beta);

    // 3. l2 normalize q, k per head
    l2norm_kernel<<<(ROWS * Hh) / 8, 256>>>(q);
    l2norm_kernel<<<(ROWS * Hh) / 8, 256>>>(k);

    // 4. sequential delta-rule scan
    scan_kernel<<<Bb * Hh, Dd>>>(q, k, v, beta, o);

    // 5. x1 = x + (gate*o) @ o_w.T   -> out
    gemm_one<0,true,true><<<grid_c, blk, GEMM_SMEM>>>(gate, o, o_w, x, out, Cc, Cc);

    // 6. xn2 = rmsnorm(x1, norm2_w)
    rmsnorm_kernel<<<ROWS, 256>>>(out, norm2_w, xn);

    // 7. FFN: g = silu(xn2 @ Wg.T); u = xn2 @ Wu.T; out += (g*u) @ Wd.T
    gemm_gu<<<grid_gu, blk, GEMM_SMEM>>>(xn, ffn_gate, ffn_up, g, u);
    gemm_one<0,true,true><<<grid_c, blk, GEMM_SMEM>>>(g, u, ffn_down, out, out, Cc, FFN);
}

// round 8
// speedup vs baseline: 3.3420x; 2.0344x over previous
#include <cuda_runtime.h>
#include <cuda_fp16.h>
#include <math.h>
#include <stdint.h>

// Problem constants
#define Bb 4
#define Tt 2048
#define Cc 1024
#define Hh 16
#define Dd 64
#define FFN 4096
#define ROWS (Bb*Tt)          // 8192

// ---------------- scratch (device globals; no allocation allowed) ----------
__device__ float g_q   [ROWS*Cc];
__device__ float g_k   [ROWS*Cc];
__device__ float g_v   [ROWS*Cc];
__device__ float g_gate[ROWS*Cc];
__device__ float g_o   [ROWS*Cc];
__device__ float g_beta[ROWS*Hh];

__device__ __half h_xn [ROWS*Cc];
__device__ __half h_ao [ROWS*Cc];
__device__ __half h_g  [ROWS*FFN];
__device__ __half h_u  [ROWS*FFN];
__device__ __half h_qw [Cc*Cc];
__device__ __half h_kw [Cc*Cc];
__device__ __half h_vw [Cc*Cc];
__device__ __half h_gw [Cc*Cc];
__device__ __half h_ow [Cc*Cc];
__device__ __half h_fg [FFN*Cc];
__device__ __half h_fu [FFN*Cc];
__device__ __half h_fd [Cc*FFN];

// ---------------- helpers ----------------
__device__ __forceinline__ float sigmoidf_(float v) { return 1.f / (1.f + __expf(-v)); }

__device__ __forceinline__ uint32_t smem_u32(const void* p) {
    uint32_t a;
    asm("{ .reg .u64 t; cvta.to.shared.u64 t, %1; cvt.u32.u64 %0, t; }" : "=r"(a) : "l"(p));
    return a;
}
__device__ __forceinline__ void cp_async16(uint32_t dst, const void* src) {
    asm volatile("cp.async.cg.shared.global [%0], [%1], 16;" :: "r"(dst), "l"(src) : "memory");
}
__device__ __forceinline__ void cp_commit() {
    asm volatile("cp.async.commit_group;" ::: "memory");
}
__device__ __forceinline__ void mma_fp16(float* d, const uint32_t* a, const uint32_t* b) {
    asm volatile(
        "mma.sync.aligned.m16n8k16.row.col.f32.f16.f16.f32 "
        "{%0,%1,%2,%3}, {%4,%5,%6,%7}, {%8,%9}, {%0,%1,%2,%3};"
        : "+f"(d[0]), "+f"(d[1]), "+f"(d[2]), "+f"(d[3])
        : "r"(a[0]), "r"(a[1]), "r"(a[2]), "r"(a[3]), "r"(b[0]), "r"(b[1]));
}

// ---------------- elementwise converters ----------------
__global__ void __launch_bounds__(256) f2h_kernel(const float* __restrict__ s,
                                                  __half* __restrict__ d, int n) {
    int i = (blockIdx.x * 256 + threadIdx.x) * 4;
    if (i < n) {
        float4 v = *(const float4*)(s + i);
        *(__half2*)(d + i)     = __floats2half2_rn(v.x, v.y);
        *(__half2*)(d + i + 2) = __floats2half2_rn(v.z, v.w);
    }
}
// ao = half(gate * o)
__global__ void __launch_bounds__(256) ao_kernel(const float* __restrict__ g,
                                                 const float* __restrict__ o,
                                                 __half* __restrict__ d) {
    int i = (blockIdx.x * 256 + threadIdx.x) * 4;
    float4 gv = *(const float4*)(g + i);
    float4 ov = *(const float4*)(o + i);
    *(__half2*)(d + i)     = __floats2half2_rn(gv.x * ov.x, gv.y * ov.y);
    *(__half2*)(d + i + 2) = __floats2half2_rn(gv.z * ov.z, gv.w * ov.w);
}
// g *= u (half2, in place)
__global__ void __launch_bounds__(256) gu_kernel(__half2* __restrict__ g,
                                                 const __half2* __restrict__ u) {
    int i = blockIdx.x * 256 + threadIdx.x;
    g[i] = __hmul2(g[i], u[i]);
}

// ---------------- RMSNorm: fp32 in, fp16 out; one block per row ------------
__global__ void __launch_bounds__(256) rmsnorm_kernel(const float* __restrict__ x,
                                                      const float* __restrict__ w,
                                                      __half* __restrict__ y) {
    int row = blockIdx.x;
    const float4* xr = (const float4*)(x + (size_t)row * Cc);
    const float4* wr = (const float4*)w;
    int tid = threadIdx.x;
    float4 v = xr[tid];
    float s = v.x*v.x + v.y*v.y + v.z*v.z + v.w*v.w;
    #pragma unroll
    for (int off = 16; off; off >>= 1) s += __shfl_xor_sync(0xffffffffu, s, off);
    __shared__ float red[8];
    int wid = tid >> 5, lane = tid & 31;
    if (lane == 0) red[wid] = s;
    __syncthreads();
    float tot = 0.f;
    #pragma unroll
    for (int i = 0; i < 8; i++) tot += red[i];
    float inv = rsqrtf(tot * (1.f / Cc) + 1e-6f);
    float4 wv = wr[tid];
    __half2* yr = (__half2*)(y + (size_t)row * Cc);
    yr[tid*2]   = __floats2half2_rn(v.x * inv * wv.x, v.y * inv * wv.y);
    yr[tid*2+1] = __floats2half2_rn(v.z * inv * wv.z, v.w * inv * wv.w);
}

// ---------------- L2 norm over last dim (64); blockIdx.y picks q/k ---------
__global__ void __launch_bounds__(256) l2norm_kernel(float* __restrict__ q,
                                                     float* __restrict__ k) {
    float* p0 = blockIdx.y ? k : q;
    int vec = blockIdx.x * 8 + (threadIdx.x >> 5);
    int lane = threadIdx.x & 31;
    float2* p = (float2*)(p0 + (size_t)vec * Dd) + lane;
    float2 v = *p;
    float s = v.x*v.x + v.y*v.y;
    #pragma unroll
    for (int off = 16; off; off >>= 1) s += __shfl_xor_sync(0xffffffffu, s, off);
    float inv = 1.f / fmaxf(sqrtf(s), 1e-12f);
    v.x *= inv; v.y *= inv;
    *p = v;
}

// ---------------- beta = sigmoid(xn @ beta_w.T + beta_b); xn is fp16 -------
__global__ void __launch_bounds__(512) beta_kernel(const __half* __restrict__ xn,
                                                   const float* __restrict__ bw,
                                                   const float* __restrict__ bb,
                                                   float* __restrict__ beta) {
    int row = blockIdx.x;
    __shared__ float xs[Cc];
    int tid = threadIdx.x;
    __half2 hv = ((const __half2*)(xn + (size_t)row * Cc))[tid];
    float2 f = __half22float2(hv);
    xs[tid*2] = f.x; xs[tid*2+1] = f.y;
    __syncthreads();
    int w = tid >> 5, lane = tid & 31;
    const float* wr = bw + (size_t)w * Cc;
    float s = 0.f;
    #pragma unroll 8
    for (int c = lane; c < Cc; c += 32) s += xs[c] * wr[c];
    #pragma unroll
    for (int off = 16; off; off >>= 1) s += __shfl_xor_sync(0xffffffffu, s, off);
    if (lane == 0) beta[(size_t)row * Hh + w] = sigmoidf_(s + bb[w]);
}

// ---------------- GatedDeltaNet scan: one block/(b,h), 128 threads ---------
// Thread pair (2*d, 2*d+1) owns state row d split in k-halves; prefetched
// global loads hide latency; double-buffered smem -> one bar/step.
__global__ void __launch_bounds__(128) scan_kernel(const float* __restrict__ q,
                                                   const float* __restrict__ k,
                                                   const float* __restrict__ v,
                                                   const float* __restrict__ beta,
                                                   float* __restrict__ o) {
    int b = blockIdx.x >> 4;
    int h = blockIdx.x & 15;
    int tid = threadIdx.x;
    int d  = tid >> 1;
    int hf = tid & 1;
    const size_t base  = ((size_t)b * Tt) * Cc + h * Dd;
    const size_t bbase = (size_t)b * Tt * Hh + h;
    __shared__ float qs[2][Dd], ks[2][Dd];
    float Mr[32];
    #pragma unroll
    for (int c = 0; c < 32; c++) Mr[c] = 0.f;

    // prefetch t = 0
    float pA = (tid < 64) ? q[base + tid] : k[base + (tid - 64)];
    float pV = v[base + d];
    float pB = beta[bbase];

    for (int t = 0; t < Tt; t++) {
        int buf = t & 1;
        if (tid < 64) qs[buf][tid] = pA; else ks[buf][tid - 64] = pA;
        float vv = pV, bt = pB;
        __syncthreads();

        // prefetch t+1 (issued early; consumed next iteration)
        int tn = (t + 1 < Tt) ? (t + 1) : t;
        size_t nb = base + (size_t)tn * Cc;
        pA = (tid < 64) ? q[nb + tid] : k[nb + (tid - 64)];
        pV = v[nb + d];
        pB = beta[bbase + (size_t)tn * Hh];

        const float* qrow = &qs[buf][hf * 32];
        const float* krow = &ks[buf][hf * 32];
        float oacc = 0.f, kacc = 0.f;
        #pragma unroll
        for (int c = 0; c < 32; c++) {
            oacc += Mr[c] * qrow[c];
            kacc += Mr[c] * krow[c];
        }
        oacc += __shfl_xor_sync(0xffffffffu, oacc, 1);
        kacc += __shfl_xor_sync(0xffffffffu, kacc, 1);
        float coef = bt * (vv - kacc);
        #pragma unroll
        for (int c = 0; c < 32; c++) Mr[c] += coef * krow[c];
        if (hf == 0) o[base + (size_t)t * Cc + d] = oacc;
    }
}

// ============ fp16 mma.sync GEMM (NT): C = epi(A*B^T) (+res) ===============
// A: M x K fp16 row-major; B: N x K fp16 row-major.
// Tile 128x128x32 halves, 256 threads = 8 warps (4m x 2n), warp tile 32x64.
// SMEM rows of 40 halves (80B): conflict-free __half2 fragment loads.
// 3-stage cp.async ring. epi: 0 none, 1 sigmoid, 2 silu
#define HSTRIDE 40
#define HTILE   (128 * HSTRIDE)       // halves per tile = 5120
#define HTILE_B (HTILE * 2)           // 10240 bytes
#define HSTAGE_B (2 * HTILE_B)        // A+B = 20480
#define GEMM_SMEM (3 * HSTAGE_B)      // 61440

template<bool HAS_RES, bool OUT_HALF>
__device__ __forceinline__ void gemm_core(const __half* __restrict__ A,
                                          const __half* __restrict__ B,
                                          const float* __restrict__ res,
                                          void* __restrict__ Cout,
                                          int N, int K, int epi) {
    extern __shared__ __half hsm[];
    const uint32_t s0 = smem_u32(hsm);

    const int tid  = threadIdx.x;
    const int wid  = tid >> 5;
    const int lane = tid & 31;
    const int warp_m = wid >> 1;
    const int warp_n = wid & 1;
    const int gid  = lane >> 2;
    const int qid  = lane & 3;

    const int brow = blockIdx.y * 128;
    const int bcol = blockIdx.x * 128;

    const __half* Aptr = A + (size_t)brow * K;
    const __half* Bptr = B + (size_t)bcol * K;

    float acc[2][8][4];
    #pragma unroll
    for (int m = 0; m < 2; m++)
        #pragma unroll
        for (int n = 0; n < 8; n++)
            #pragma unroll
            for (int c = 0; c < 4; c++) acc[m][n][c] = 0.f;

    const int nk = K >> 5;

    auto fill = [&](int kb, int st) {
        const uint32_t aB = s0 + st * HSTAGE_B;
        const uint32_t bB = aB + HTILE_B;
        const int koff = kb * 32;
        #pragma unroll
        for (int i = 0; i < 2; i++) {
            int c = tid + i * 256;            // 512 chunks of 8 halves
            int row = c >> 2, cp = c & 3;
            cp_async16(aB + row * 80 + cp * 16, Aptr + (size_t)row * K + koff + cp * 8);
        }
        #pragma unroll
        for (int i = 0; i < 2; i++) {
            int c = tid + i * 256;
            int row = c >> 2, cp = c & 3;
            cp_async16(bB + row * 80 + cp * 16, Bptr + (size_t)row * K + koff + cp * 8);
        }
        cp_commit();
    };

    fill(0, 0);
    fill(1, 1);

    int cur = 0;
    for (int kb = 0; kb < nk; kb++) {
        if (kb == nk - 1)
            asm volatile("cp.async.wait_group 0;" ::: "memory");
        else
            asm volatile("cp.async.wait_group 1;" ::: "memory");
        __syncthreads();

        const __half* sA = hsm + cur * (HSTAGE_B / 2);
        const __half* sB = sA + HTILE;

        #pragma unroll
        for (int ks = 0; ks < 2; ks++) {
            const int k0 = ks * 16 + qid * 2;
            uint32_t afr[2][4];
            #pragma unroll
            for (int m = 0; m < 2; m++) {
                int r = warp_m * 32 + m * 16 + gid;
                afr[m][0] = *(const uint32_t*)(sA + (r)     * HSTRIDE + k0);
                afr[m][1] = *(const uint32_t*)(sA + (r + 8) * HSTRIDE + k0);
                afr[m][2] = *(const uint32_t*)(sA + (r)     * HSTRIDE + k0 + 8);
                afr[m][3] = *(const uint32_t*)(sA + (r + 8) * HSTRIDE + k0 + 8);
            }
            #pragma unroll
            for (int n = 0; n < 8; n++) {
                int cn = warp_n * 64 + n * 8 + gid;
                uint32_t bfr[2];
                bfr[0] = *(const uint32_t*)(sB + cn * HSTRIDE + k0);
                bfr[1] = *(const uint32_t*)(sB + cn * HSTRIDE + k0 + 8);
                mma_fp16(acc[0][n], afr[0], bfr);
                mma_fp16(acc[1][n], afr[1], bfr);
            }
        }

        if (kb + 2 < nk) {
            __syncthreads();
            fill(kb + 2, (kb + 2) % 3);
        }
        cur = (cur + 1) % 3;
    }

    // ---- epilogue ----
    #pragma unroll
    for (int m = 0; m < 2; m++) {
        const size_t r0 = (size_t)(brow + warp_m * 32 + m * 16 + gid);
        const size_t r1 = r0 + 8;
        #pragma unroll
        for (int n = 0; n < 8; n++) {
            const int col = bcol + warp_n * 64 + n * 8 + qid * 2;
            float v0 = acc[m][n][0], v1 = acc[m][n][1];
            float v2 = acc[m][n][2], v3 = acc[m][n][3];
            if (epi == 1) {
                v0 = sigmoidf_(v0); v1 = sigmoidf_(v1);
                v2 = sigmoidf_(v2); v3 = sigmoidf_(v3);
            } else if (epi == 2) {
                v0 *= sigmoidf_(v0); v1 *= sigmoidf_(v1);
                v2 *= sigmoidf_(v2); v3 *= sigmoidf_(v3);
            }
            if (HAS_RES) {
                float2 ra = *(const float2*)(res + r0 * N + col);
                float2 rb = *(const float2*)(res + r1 * N + col);
                v0 += ra.x; v1 += ra.y; v2 += rb.x; v3 += rb.y;
            }
            if (OUT_HALF) {
                __half* C = (__half*)Cout;
                *(__half2*)(C + r0 * N + col) = __floats2half2_rn(v0, v1);
                *(__half2*)(C + r1 * N + col) = __floats2half2_rn(v2, v3);
            } else {
                float* C = (float*)Cout;
                *(float2*)(C + r0 * N + col) = make_float2(v0, v1);
                *(float2*)(C + r1 * N + col) = make_float2(v2, v3);
            }
        }
    }
}

// q/k/v/gate fused: blockIdx.z selects; z==3 -> sigmoid
__global__ void __launch_bounds__(256) gemm_qkvg(const __half* __restrict__ A,
                                                 const __half* __restrict__ B0,
                                                 const __half* __restrict__ B1,
                                                 const __half* __restrict__ B2,
                                                 const __half* __restrict__ B3,
                                                 float* __restrict__ C0,
                                                 float* __restrict__ C1,
                                                 float* __restrict__ C2,
                                                 float* __restrict__ C3) {
    int z = blockIdx.z;
    const __half* B = (z == 0) ? B0 : (z == 1) ? B1 : (z == 2) ? B2 : B3;
    float*        C = (z == 0) ? C0 : (z == 1) ? C1 : (z == 2) ? C2 : C3;
    gemm_core<false, false>(A, B, nullptr, C, Cc, Cc, (z == 3) ? 1 : 0);
}

// ffn gate/up fused: z==0 silu->g(half), z==1 plain->u(half)
__global__ void __launch_bounds__(256) gemm_gu(const __half* __restrict__ A,
                                               const __half* __restrict__ Bg,
                                               const __half* __restrict__ Bu,
                                               __half* __restrict__ Cg,
                                               __half* __restrict__ Cu) {
    int z = blockIdx.z;
    gemm_core<false, true>(A, z ? Bu : Bg, nullptr, z ? Cu : Cg, FFN, Cc, z ? 0 : 2);
}

// plain + residual, fp32 out (o-proj, down-proj)
__global__ void __launch_bounds__(256) gemm_res(const __half* __restrict__ A,
                                                const __half* __restrict__ B,
                                                const float* __restrict__ res,
                                                float* __restrict__ C,
                                                int N, int K) {
    gemm_core<true, false>(A, B, res, C, N, K, 0);
}

// ---------------- launcher ----------------
extern "C" void kernel_launch(void* const* d_in, const int* in_sizes, int n_in,
                              void* d_out, int out_size) {
    const float* x        = (const float*)d_in[0];
    // d_in[1]=cos, d_in[2]=sin  (unused for layer_idx=0)
    const float* norm1_w  = (const float*)d_in[3];
    const float* norm2_w  = (const float*)d_in[4];
    const float* q_w      = (const float*)d_in[5];
    const float* k_w      = (const float*)d_in[6];
    const float* v_w      = (const float*)d_in[7];
    const float* beta_w   = (const float*)d_in[8];
    const float* beta_b   = (const float*)d_in[9];
    const float* gate_w   = (const float*)d_in[10];
    const float* o_w      = (const float*)d_in[11];
    const float* ffn_gate = (const float*)d_in[12];
    const float* ffn_up   = (const float*)d_in[13];
    const float* ffn_down = (const float*)d_in[14];
    float* out = (float*)d_out;

    float *q, *k, *v, *gate, *o, *beta;
    __half *xn16, *ao16, *g16, *u16, *qw16, *kw16, *vw16, *gw16, *ow16, *fg16, *fu16, *fd16;
    cudaGetSymbolAddress((void**)&q,    g_q);
    cudaGetSymbolAddress((void**)&k,    g_k);
    cudaGetSymbolAddress((void**)&v,    g_v);
    cudaGetSymbolAddress((void**)&gate, g_gate);
    cudaGetSymbolAddress((void**)&o,    g_o);
    cudaGetSymbolAddress((void**)&beta, g_beta);
    cudaGetSymbolAddress((void**)&xn16, h_xn);
    cudaGetSymbolAddress((void**)&ao16, h_ao);
    cudaGetSymbolAddress((void**)&g16,  h_g);
    cudaGetSymbolAddress((void**)&u16,  h_u);
    cudaGetSymbolAddress((void**)&qw16, h_qw);
    cudaGetSymbolAddress((void**)&kw16, h_kw);
    cudaGetSymbolAddress((void**)&vw16, h_vw);
    cudaGetSymbolAddress((void**)&gw16, h_gw);
    cudaGetSymbolAddress((void**)&ow16, h_ow);
    cudaGetSymbolAddress((void**)&fg16, h_fg);
    cudaGetSymbolAddress((void**)&fu16, h_fu);
    cudaGetSymbolAddress((void**)&fd16, h_fd);

    cudaFuncSetAttribute(gemm_qkvg, cudaFuncAttributeMaxDynamicSharedMemorySize, GEMM_SMEM);
    cudaFuncSetAttribute(gemm_gu,   cudaFuncAttributeMaxDynamicSharedMemorySize, GEMM_SMEM);
    cudaFuncSetAttribute(gemm_res,  cudaFuncAttributeMaxDynamicSharedMemorySize, GEMM_SMEM);

    const int CC2 = Cc * Cc;          // 1M
    const int CF  = FFN * Cc;         // 4M

    // 0. weight conversions fp32 -> fp16
    f2h_kernel<<<CC2/1024, 256>>>(q_w,      qw16, CC2);
    f2h_kernel<<<CC2/1024, 256>>>(k_w,      kw16, CC2);
    f2h_kernel<<<CC2/1024, 256>>>(v_w,      vw16, CC2);
    f2h_kernel<<<CC2/1024, 256>>>(gate_w,   gw16, CC2);
    f2h_kernel<<<CC2/1024, 256>>>(o_w,      ow16, CC2);
    f2h_kernel<<<CF/1024,  256>>>(ffn_gate, fg16, CF);
    f2h_kernel<<<CF/1024,  256>>>(ffn_up,   fu16, CF);
    f2h_kernel<<<CF/1024,  256>>>(ffn_down, fd16, CF);

    dim3 blk(256);
    dim3 grid_qkvg(Cc / 128, ROWS / 128, 4);
    dim3 grid_c(Cc / 128, ROWS / 128);
    dim3 grid_gu(FFN / 128, ROWS / 128, 2);

    // 1. xn1 = rmsnorm(x, norm1_w) -> fp16
    rmsnorm_kernel<<<ROWS, 256>>>(x, norm1_w, xn16);

    // 2. fused q/k/v/gate projections (+ sigmoid on gate)
    gemm_qkvg<<<grid_qkvg, blk, GEMM_SMEM>>>(xn16, qw16, kw16, vw16, gw16, q, k, v, gate);
    beta_kernel<<<ROWS, 512>>>(xn16, beta_w, beta_b, beta);

    // 3. l2 normalize q, k per head (one launch)
    l2norm_kernel<<<dim3((ROWS * Hh) / 8, 2), 256>>>(q, k);

    // 4. sequential delta-rule scan
    scan_kernel<<<Bb * Hh, 128>>>(q, k, v, beta, o);

    // 5. ao = half(gate*o);  x1 = x + ao @ o_w.T -> out
    ao_kernel<<<(ROWS * Cc) / 1024, 256>>>(gate, o, ao16);
    gemm_res<<<grid_c, blk, GEMM_SMEM>>>(ao16, ow16, x, out, Cc, Cc);

    // 6. xn2 = rmsnorm(x1, norm2_w) -> fp16
    rmsnorm_kernel<<<ROWS, 256>>>(out, norm2_w, xn16);

    // 7. FFN: g = silu(xn2@Wg.T), u = xn2@Wu.T (half); g *= u; out += g @ Wd.T
    gemm_gu<<<grid_gu, blk, GEMM_SMEM>>>(xn16, fg16, fu16, g16, u16);
    gu_kernel<<<(ROWS * FFN) / 512, 256>>>((__half2*)g16, (const __half2*)u16);
    gemm_res<<<grid_c, blk, GEMM_SMEM>>>(g16, fd16, out, out, Cc, FFN);
}